// round 6
// baseline (speedup 1.0000x reference)
#include <cuda_runtime.h>
#include <cuda_bf16.h>

// Problem constants
#define B 4
#define P 12000
#define C 64
#define H 512
#define W 512
#define TILE_X 128
#define SLOT_CAP 20   // staged rows per 128-px tile (mean occ 5.9; +6 sigma)

// Winner pillar map per output pixel, encoded as (p+1); 0 = empty.
// Zero-initialized at module load; gather kernel restores its strip to 0
// (read-then-clear by the SAME thread => ordered), so the all-zeros
// invariant holds before every kernel_launch call / graph replay.
__device__ int g_winner[B * H * W];

// Kernel 1: one thread per (b, p). Reference semantics: sequential .at[].set
// means the LARGEST pillar index wins per pixel -> atomicMax on (p+1).
__global__ void scatter_winner_kernel(const int* __restrict__ coords) {
    int i = blockIdx.x * blockDim.x + threadIdx.x;   // i = b*P + p
    if (i >= B * P) return;
    int b = i / P;
    int p = i - b * P;
    int4 c4 = reinterpret_cast<const int4*>(coords)[i];  // (batch, y, x, z)
    int y = c4.y;
    int x = c4.z;
    if ((unsigned)x < (unsigned)W && (unsigned)y < (unsigned)H) {
        atomicMax(&g_winner[(b * H + y) * W + x], p + 1);
    }
}

// Kernel 2: one 128-thread block per (b, y, 256-px x half-row) = TWO tiles.
// Prologue batching: both winner loads issued at cycle 0 (warps 0/1),
// ballot-based compaction (no smem atomics), one combined feature-staging
// phase, then two back-to-back 32 KB select-free emit bursts.
__global__ __launch_bounds__(128) void gather_out_kernel(
    const float* __restrict__ feat, float* __restrict__ out) {
    __shared__ int   s_slot[2][TILE_X];  // >=0: slot | -1: empty | <=-2: pid=-(s)-2
    __shared__ int   s_pid[2][SLOT_CAP];
    __shared__ int   s_n[2];
    // rows [0,CAP)=tile0, [CAP,2CAP)=tile1, row 2CAP = shared zero row; pad 65
    __shared__ float s_feat[(2 * SLOT_CAP + 1) * 65];

    const int b    = blockIdx.z;
    const int y    = blockIdx.y;
    const int x0   = blockIdx.x * (2 * TILE_X);     // 256-px half row
    const int tid  = threadIdx.x;
    const int wid  = tid >> 5;
    const int lane = tid & 31;

    const float* featb = feat + (size_t)b * P * C;

    // --- Phase 1: warps 0/1 read+clear+compact their tile; warps 2/3 zero-row.
    if (wid < 2) {
        int4* wrow4 = reinterpret_cast<int4*>(
            g_winner + (b * H + y) * W + x0 + wid * TILE_X);
        int4 w4 = wrow4[lane];              // issued immediately, both tiles
        wrow4[lane] = make_int4(0, 0, 0, 0); // same thread as reader => ordered

        const int wv[4] = {w4.x, w4.y, w4.z, w4.w};
        const unsigned lt = (1u << lane) - 1u;
        int base = 0;
        #pragma unroll
        for (int j = 0; j < 4; ++j) {
            const bool occ = (wv[j] > 0);
            const unsigned m = __ballot_sync(0xFFFFFFFFu, occ);
            int s = -1;
            if (occ) {
                int sl = base + __popc(m & lt);
                if (sl < SLOT_CAP) { s_pid[wid][sl] = wv[j] - 1; s = sl; }
                else               { s = -(wv[j] + 1); }   // pid = -s - 2
            }
            s_slot[wid][lane * 4 + j] = s;
            base += __popc(m);
        }
        if (lane == 0) s_n[wid] = base;
    } else if (tid >= 64 && tid < 64 + 65) {
        s_feat[2 * SLOT_CAP * 65 + (tid - 64)] = 0.0f;   // zero row
    }
    __syncthreads();

    // --- Phase 2: combined staging of both tiles (coalesced float4 loads).
    const float4* featb4 = reinterpret_cast<const float4*>(featb);
    const int n0 = min(s_n[0], SLOT_CAP);
    const int n1 = min(s_n[1], SLOT_CAP);
    const int total_q = (n0 + n1) * (C / 4);
    for (int i = tid; i < total_q; i += 128) {
        int sl = i >> 4;          // C/4 == 16
        int q  = i & 15;
        int pid = (sl < n0) ? s_pid[0][sl] : s_pid[1][sl - n0];
        int row = (sl < n0) ? sl            : SLOT_CAP + (sl - n0);
        float4 v = __ldg(&featb4[(size_t)pid * (C / 4) + q]);
        float* dst = &s_feat[row * 65 + q * 4];
        dst[0] = v.x; dst[1] = v.y; dst[2] = v.z; dst[3] = v.w;
    }
    __syncthreads();

    // --- Phase 3: two back-to-back emit bursts. lane = x-quad, warp = c0.
    const int c0 = wid;                        // 0..3, channels c0 + 4*it
    const size_t step = (size_t)4 * H * (W / 4);

    #pragma unroll
    for (int t = 0; t < 2; ++t) {
        const int rbase = t * SLOT_CAP;
        const int px = lane * 4;
        const int s0 = s_slot[t][px + 0];
        const int s1 = s_slot[t][px + 1];
        const int s2 = s_slot[t][px + 2];
        const int s3 = s_slot[t][px + 3];

        float4* dst = reinterpret_cast<float4*>(out)
                    + ((size_t)(b * C + c0) * H + y) * (W / 4)
                    + (x0 + t * TILE_X) / 4 + lane;

        if (s_n[t] <= SLOT_CAP) {
            const float* f0 = s_feat + (s0 >= 0 ? rbase + s0 : 2 * SLOT_CAP) * 65;
            const float* f1 = s_feat + (s1 >= 0 ? rbase + s1 : 2 * SLOT_CAP) * 65;
            const float* f2 = s_feat + (s2 >= 0 ? rbase + s2 : 2 * SLOT_CAP) * 65;
            const float* f3 = s_feat + (s3 >= 0 ? rbase + s3 : 2 * SLOT_CAP) * 65;
            #pragma unroll 8
            for (int it = 0; it < 16; ++it) {
                const int c = c0 + 4 * it;
                float4 v = make_float4(f0[c], f1[c], f2[c], f3[c]);
                __stcs(dst, v);
                dst += step;
            }
        } else {
            // Statistically-never slow path (>SLOT_CAP occupied px in a tile).
            #pragma unroll 4
            for (int it = 0; it < 16; ++it) {
                const int c = c0 + 4 * it;
                float4 v;
                v.x = (s0 >= 0) ? s_feat[(rbase + s0) * 65 + c]
                    : (s0 == -1) ? 0.0f : featb[(size_t)(-s0 - 2) * C + c];
                v.y = (s1 >= 0) ? s_feat[(rbase + s1) * 65 + c]
                    : (s1 == -1) ? 0.0f : featb[(size_t)(-s1 - 2) * C + c];
                v.z = (s2 >= 0) ? s_feat[(rbase + s2) * 65 + c]
                    : (s2 == -1) ? 0.0f : featb[(size_t)(-s2 - 2) * C + c];
                v.w = (s3 >= 0) ? s_feat[(rbase + s3) * 65 + c]
                    : (s3 == -1) ? 0.0f : featb[(size_t)(-s3 - 2) * C + c];
                __stcs(dst, v);
                dst += step;
            }
        }
    }
}

extern "C" void kernel_launch(void* const* d_in, const int* in_sizes, int n_in,
                              void* d_out, int out_size) {
    const float* feat   = (const float*)d_in[0];   // [B, P, C] fp32
    const int*   coords = (const int*)d_in[1];     // [B, P, 4] int32
    float* out = (float*)d_out;                    // [B, C, H, W] fp32

    scatter_winner_kernel<<<(B * P + 255) / 256, 256>>>(coords);

    dim3 grid(W / (2 * TILE_X), H, B);   // 4096 blocks, 2 tiles each
    gather_out_kernel<<<grid, 128>>>(feat, out);
}